// round 6
// baseline (speedup 1.0000x reference)
#include <cuda_runtime.h>

#define B   32
#define T   100
#define V   10000
#define D   128
#define OUTN 1000
#define BT  (B*T)

typedef unsigned long long u64;

// ---------------- scratch (no allocations allowed) ----------------
__device__ float d_e[BT * D];          // embedded visits [B*T][128]
__device__ int   d_mask[BT];           // visit mask
__device__ float d_x3[BT * 768];       // input-side gates, [bt][dir*384 + g]
__device__ float d_hs[2 * BT * D];     // GRU outputs, dir-major
__device__ float d_ctx[B * 512];       // [c(256) | h_last(256)] per batch
__device__ float d_feat[B * D];        // combined feature

// ---------------- helpers ----------------
__device__ __forceinline__ u64 ffma2(u64 a, u64 b, u64 c) {
    u64 d;
    asm("fma.rn.f32x2 %0, %1, %2, %3;" : "=l"(d) : "l"(a), "l"(b), "l"(c));
    return d;
}
__device__ __forceinline__ float2 u2f2(u64 a) {
    float2 f;
    asm("mov.b64 {%0, %1}, %2;" : "=f"(f.x), "=f"(f.y) : "l"(a));
    return f;
}
__device__ __forceinline__ float fast_sigmoid(float x) {
    return 1.0f / (1.0f + __expf(-x));
}
__device__ __forceinline__ float fast_tanh(float x) {
    return 2.0f / (1.0f + __expf(-2.0f * x)) - 1.0f;
}

// ---------------- 1) sparse embedding + mask ----------------
__global__ void embed_kernel(const float* __restrict__ x, const float* __restrict__ emb) {
    int bt = blockIdx.x;
    __shared__ int cnt;
    __shared__ int idx[1024];
    __shared__ float part[128];
    if (threadIdx.x == 0) cnt = 0;
    __syncthreads();

    const float4* row = reinterpret_cast<const float4*>(x + (size_t)bt * V);
    for (int i = threadIdx.x; i < V / 4; i += blockDim.x) {
        float4 v = row[i];
        if (v.x != 0.f) { int p = atomicAdd(&cnt, 1); if (p < 1024) idx[p] = 4 * i; }
        if (v.y != 0.f) { int p = atomicAdd(&cnt, 1); if (p < 1024) idx[p] = 4 * i + 1; }
        if (v.z != 0.f) { int p = atomicAdd(&cnt, 1); if (p < 1024) idx[p] = 4 * i + 2; }
        if (v.w != 0.f) { int p = atomicAdd(&cnt, 1); if (p < 1024) idx[p] = 4 * i + 3; }
    }
    __syncthreads();
    int n = min(cnt, 1024);
    int d = threadIdx.x & 127;
    int half = threadIdx.x >> 7;
    float acc = 0.f;
    for (int j = half; j < n; j += 2) acc += emb[(size_t)idx[j] * D + d];
    if (half) part[d] = acc;
    __syncthreads();
    float tot = 0.f;
    if (half == 0) {
        tot = acc + part[d];
        d_e[bt * D + d] = tot;
    }
    int nz = __syncthreads_or(half == 0 && tot != 0.f);
    if (threadIdx.x == 0) d_mask[bt] = nz ? 1 : 0;
}

// ---------------- 2) x3 = e @ wih^T + bih, both dirs ----------------
// grid (100, 8, 2), 256 threads. tile: 32 bt-rows x 48 gate-cols, K=128.
#define ES 132  // padded row stride, 16B-aligned for LDS.128
__global__ void xgemm_kernel(const float* __restrict__ wih_f, const float* __restrict__ wih_b,
                             const float* __restrict__ bih_f, const float* __restrict__ bih_b) {
    const int bt0  = blockIdx.x * 32;
    const int col0 = blockIdx.y * 48;
    const int dir  = blockIdx.z;
    const float* W  = dir ? wih_b : wih_f;
    const float* bi = dir ? bih_b : bih_f;

    __shared__ __align__(16) float e_sh[32 * ES];
    __shared__ __align__(16) float w_sh[48 * ES];
    int tid = threadIdx.x;
    for (int i = tid; i < 32 * 32; i += 256) {          // float4 granularity
        int r = i >> 5, k4 = i & 31;
        *reinterpret_cast<float4*>(&e_sh[r * ES + 4 * k4]) =
            *reinterpret_cast<const float4*>(&d_e[(bt0 + r) * D + 4 * k4]);
    }
    for (int i = tid; i < 48 * 32; i += 256) {
        int c = i >> 5, k4 = i & 31;
        *reinterpret_cast<float4*>(&w_sh[c * ES + 4 * k4]) =
            *reinterpret_cast<const float4*>(&W[(size_t)(col0 + c) * D + 4 * k4]);
    }
    __syncthreads();

    int rt = tid & 15;   // rows 2*rt, 2*rt+1
    int ct = tid >> 4;   // cols 3*ct .. 3*ct+2
    int r0 = rt * 2, c0 = ct * 3;

    u64 accP[2][3] = {}, accQ[2][3] = {};
    for (int k = 0; k < 128; k += 4) {
        ulonglong2 ev[2], wv[3];
#pragma unroll
        for (int i = 0; i < 2; i++)
            ev[i] = *reinterpret_cast<const ulonglong2*>(&e_sh[(r0 + i) * ES + k]);
#pragma unroll
        for (int c = 0; c < 3; c++)
            wv[c] = *reinterpret_cast<const ulonglong2*>(&w_sh[(c0 + c) * ES + k]);
#pragma unroll
        for (int i = 0; i < 2; i++)
#pragma unroll
            for (int c = 0; c < 3; c++) {
                accP[i][c] = ffma2(ev[i].x, wv[c].x, accP[i][c]);
                accQ[i][c] = ffma2(ev[i].y, wv[c].y, accQ[i][c]);
            }
    }
#pragma unroll
    for (int i = 0; i < 2; i++)
#pragma unroll
        for (int c = 0; c < 3; c++) {
            float2 p = u2f2(accP[i][c]), q = u2f2(accQ[i][c]);
            float v = (p.x + p.y) + (q.x + q.y) + bi[col0 + c0 + c];
            d_x3[(size_t)(bt0 + r0 + i) * 768 + dir * 384 + col0 + c0 + c] = v;
        }
}

// ---------------- 3) GRU, one CTA per (batch, dir) ----------------
// 128 threads; thread j owns ALL THREE whh gate rows (r,z,n) for hidden unit j
// in registers (192 u64, fits 512-reg cap at 128 threads). h read once per
// step as 32 LDS.128 shared across the 3 gates; double-buffered h = 1 barrier.
__global__ void __launch_bounds__(128, 1)
gru_kernel(const float* __restrict__ whh_f, const float* __restrict__ whh_b,
           const float* __restrict__ bhh_f, const float* __restrict__ bhh_b) {
    int b = blockIdx.x, dir = blockIdx.y;
    int j = threadIdx.x;
    const float* whh = dir ? whh_b : whh_f;
    const float* bhh = dir ? bhh_b : bhh_f;

    __shared__ __align__(16) float hbuf[2][128];

    u64 wrr[64], wzz[64], wnn[64];
    {
        const u64* p0 = reinterpret_cast<const u64*>(whh + (size_t)j * 128);
        const u64* p1 = reinterpret_cast<const u64*>(whh + (size_t)(128 + j) * 128);
        const u64* p2 = reinterpret_cast<const u64*>(whh + (size_t)(256 + j) * 128);
#pragma unroll
        for (int k = 0; k < 64; k++) { wrr[k] = p0[k]; wzz[k] = p1[k]; wnn[k] = p2[k]; }
    }
    float br = bhh[j], bz = bhh[128 + j], bn = bhh[256 + j];
    hbuf[0][j] = 0.f;
    float hprev = 0.f;

    const float* x3p = d_x3 + (size_t)b * T * 768 + dir * 384
                       + (dir ? (size_t)(T - 1) * 768 : 0);
    const long xstep = dir ? -768 : 768;
    float* hsp = d_hs + ((size_t)dir * BT + (size_t)b * T) * D
                 + (dir ? (size_t)(T - 1) * D : 0) + j;
    const long hstep = dir ? -(long)D : (long)D;

    float xr = x3p[j], xz = x3p[128 + j], xn = x3p[256 + j];
    __syncthreads();

    int p = 0;
    for (int s = 0; s < T; s++) {
        const ulonglong2* hv2 = reinterpret_cast<const ulonglong2*>(hbuf[p]);
        u64 ar0 = 0, ar1 = 0, ar2 = 0, ar3 = 0;
        u64 az0 = 0, az1 = 0, az2 = 0, az3 = 0;
        u64 an0 = 0, an1 = 0, an2 = 0, an3 = 0;
#pragma unroll
        for (int kc = 0; kc < 32; kc += 4) {
            ulonglong2 h0 = hv2[kc], h1 = hv2[kc + 1], h2 = hv2[kc + 2], h3 = hv2[kc + 3];
            int w = 2 * kc;
            ar0 = ffma2(wrr[w],     h0.x, ar0); ar1 = ffma2(wrr[w + 1], h0.y, ar1);
            ar2 = ffma2(wrr[w + 2], h1.x, ar2); ar3 = ffma2(wrr[w + 3], h1.y, ar3);
            ar0 = ffma2(wrr[w + 4], h2.x, ar0); ar1 = ffma2(wrr[w + 5], h2.y, ar1);
            ar2 = ffma2(wrr[w + 6], h3.x, ar2); ar3 = ffma2(wrr[w + 7], h3.y, ar3);

            az0 = ffma2(wzz[w],     h0.x, az0); az1 = ffma2(wzz[w + 1], h0.y, az1);
            az2 = ffma2(wzz[w + 2], h1.x, az2); az3 = ffma2(wzz[w + 3], h1.y, az3);
            az0 = ffma2(wzz[w + 4], h2.x, az0); az1 = ffma2(wzz[w + 5], h2.y, az1);
            az2 = ffma2(wzz[w + 6], h3.x, az2); az3 = ffma2(wzz[w + 7], h3.y, az3);

            an0 = ffma2(wnn[w],     h0.x, an0); an1 = ffma2(wnn[w + 1], h0.y, an1);
            an2 = ffma2(wnn[w + 2], h1.x, an2); an3 = ffma2(wnn[w + 3], h1.y, an3);
            an0 = ffma2(wnn[w + 4], h2.x, an0); an1 = ffma2(wnn[w + 5], h2.y, an1);
            an2 = ffma2(wnn[w + 6], h3.x, an2); an3 = ffma2(wnn[w + 7], h3.y, an3);
        }
        // prefetch next-step x (LDGs drain under the activation + barrier)
        float nxr = 0.f, nxz = 0.f, nxn = 0.f;
        if (s + 1 < T) {
            const float* xp = x3p + xstep;
            nxr = xp[j]; nxz = xp[128 + j]; nxn = xp[256 + j];
        }

        float2 r0 = u2f2(ar0), r1 = u2f2(ar1), r2 = u2f2(ar2), r3 = u2f2(ar3);
        float gr = ((r0.x + r0.y) + (r1.x + r1.y)) + ((r2.x + r2.y) + (r3.x + r3.y)) + br;
        float r = fast_sigmoid(xr + gr);
        float2 z0 = u2f2(az0), z1 = u2f2(az1), z2 = u2f2(az2), z3 = u2f2(az3);
        float gz = ((z0.x + z0.y) + (z1.x + z1.y)) + ((z2.x + z2.y) + (z3.x + z3.y)) + bz;
        float z = fast_sigmoid(xz + gz);
        float2 n0 = u2f2(an0), n1 = u2f2(an1), n2 = u2f2(an2), n3 = u2f2(an3);
        float gn = ((n0.x + n0.y) + (n1.x + n1.y)) + ((n2.x + n2.y) + (n3.x + n3.y)) + bn;
        float n = fast_tanh(xn + r * gn);
        float hnew = (1.f - z) * n + z * hprev;
        hprev = hnew;
        hbuf[p ^ 1][j] = hnew;
        *hsp = hnew;
        hsp += hstep; x3p += xstep;
        xr = nxr; xz = nxz; xn = nxn;
        __syncthreads();
        p ^= 1;
    }
}

// ---------------- 4a) attention: scores, softmax, context, h_last ----------------
__global__ void attn_kernel(const float* __restrict__ aw, const float* __restrict__ ab) {
    int b = blockIdx.x;
    int tid = threadIdx.x;  // 256
    __shared__ float aw_sh[256];
    __shared__ float sc[128];
    __shared__ int   msk[128];
    __shared__ int last_sh;

    aw_sh[tid] = aw[tid];
    if (tid < T) msk[tid] = d_mask[b * T + tid];
    __syncthreads();

    const float* hf = d_hs + (size_t)b * T * D;
    const float* hb = d_hs + ((size_t)BT + (size_t)b * T) * D;
    int w = tid >> 5, lane = tid & 31;

    for (int t = w; t < T; t += 8) {
        float s = 0.f;
        const float* pf = hf + (size_t)t * D;
        const float* pb = hb + (size_t)t * D;
#pragma unroll
        for (int d = lane; d < D; d += 32)
            s += pf[d] * aw_sh[d] + pb[d] * aw_sh[128 + d];
#pragma unroll
        for (int o = 16; o; o >>= 1) s += __shfl_xor_sync(0xffffffffu, s, o);
        if (lane == 0) sc[t] = msk[t] ? (s + ab[0]) : -1e9f;
    }
    __syncthreads();

    if (w == 0) {
        float m = -1e30f;
        for (int t = lane; t < T; t += 32) m = fmaxf(m, sc[t]);
#pragma unroll
        for (int o = 16; o; o >>= 1) m = fmaxf(m, __shfl_xor_sync(0xffffffffu, m, o));
        float s = 0.f;
        for (int t = lane; t < T; t += 32) { float e = __expf(sc[t] - m); sc[t] = e; s += e; }
#pragma unroll
        for (int o = 16; o; o >>= 1) s += __shfl_xor_sync(0xffffffffu, s, o);
        float inv = 1.f / s;
        for (int t = lane; t < T; t += 32) sc[t] *= inv;
        int c = 0;
        for (int t = lane; t < T; t += 32) c += msk[t];
#pragma unroll
        for (int o = 16; o; o >>= 1) c += __shfl_xor_sync(0xffffffffu, c, o);
        if (lane == 0) last_sh = c - 1;
    }
    __syncthreads();

    int last = last_sh;
    int f = tid;
    const float* hcol = (f < 128) ? (hf + f) : (hb + (f - 128));
    float cacc = 0.f;
#pragma unroll
    for (int t0 = 0; t0 < T; t0 += 10) {
        float p = 0.f;
#pragma unroll
        for (int u = 0; u < 10; u++)
            p += sc[t0 + u] * hcol[(size_t)(t0 + u) * D];
        cacc += p;
    }
    d_ctx[b * 512 + f] = cacc;
    d_ctx[b * 512 + 256 + f] = hcol[(size_t)last * D];
}

// ---------------- 4b) combine: feat = tanh(ctx @ comb_w^T + comb_b) ----------------
// grid (32, 8), 256 threads; CTA handles 16 outputs for one batch (2 per warp).
__global__ void comb_kernel(const float* __restrict__ comb_w, const float* __restrict__ comb_b) {
    int b = blockIdx.x, og = blockIdx.y;
    int tid = threadIdx.x, w = tid >> 5, lane = tid & 31;
    __shared__ __align__(16) float ctx[512];
    ctx[tid] = d_ctx[b * 512 + tid];
    ctx[256 + tid] = d_ctx[b * 512 + 256 + tid];
    __syncthreads();

    int o = og * 16 + 2 * w;
    const float4* rowA = reinterpret_cast<const float4*>(comb_w + (size_t)o * 512);
    const float4* rowB = reinterpret_cast<const float4*>(comb_w + (size_t)(o + 1) * 512);
    float accA = 0.f, accB = 0.f;
#pragma unroll
    for (int q = 0; q < 4; q++) {
        int i = lane + 32 * q;
        float4 wa = rowA[i];
        float4 wb = rowB[i];
        float4 iv = *reinterpret_cast<const float4*>(&ctx[4 * i]);
        accA += wa.x * iv.x + wa.y * iv.y + wa.z * iv.z + wa.w * iv.w;
        accB += wb.x * iv.x + wb.y * iv.y + wb.z * iv.z + wb.w * iv.w;
    }
#pragma unroll
    for (int of = 16; of; of >>= 1) {
        accA += __shfl_xor_sync(0xffffffffu, accA, of);
        accB += __shfl_xor_sync(0xffffffffu, accB, of);
    }
    if (lane == 0) {
        d_feat[b * D + o]     = fast_tanh(accA + comb_b[o]);
        d_feat[b * D + o + 1] = fast_tanh(accB + comb_b[o + 1]);
    }
}

// ---------------- 5) logits = feat @ fc_w^T + fc_b ----------------
#define FS 132
__global__ void logits_kernel(const float* __restrict__ fc_w, const float* __restrict__ fc_b,
                              float* __restrict__ out) {
    int o0 = blockIdx.x * 8;
    int tid = threadIdx.x;
    __shared__ __align__(16) float fsh[32 * FS];
    __shared__ __align__(16) float wsh[8 * 128];
    for (int i = tid; i < 32 * 32; i += 256) {
        int bb = i >> 5, k4 = i & 31;
        *reinterpret_cast<float4*>(&fsh[bb * FS + 4 * k4]) =
            *reinterpret_cast<const float4*>(&d_feat[bb * D + 4 * k4]);
    }
    for (int i = tid; i < 8 * 32; i += 256)
        *reinterpret_cast<float4*>(&wsh[4 * i]) =
            *reinterpret_cast<const float4*>(&fc_w[(size_t)o0 * 128 + 4 * i]);
    __syncthreads();

    int bb = tid & 31, oj = tid >> 5;
    float acc = fc_b[o0 + oj];
#pragma unroll
    for (int k = 0; k < 128; k += 4) {
        float4 fv = *reinterpret_cast<const float4*>(&fsh[bb * FS + k]);
        float4 wv = *reinterpret_cast<const float4*>(&wsh[oj * 128 + k]);
        acc += fv.x * wv.x + fv.y * wv.y + fv.z * wv.z + fv.w * wv.w;
    }
    out[(size_t)bb * OUTN + o0 + oj] = acc;
}

// ---------------- launch ----------------
extern "C" void kernel_launch(void* const* d_in, const int* in_sizes, int n_in,
                              void* d_out, int out_size) {
    const float* x      = (const float*)d_in[0];
    const float* emb    = (const float*)d_in[1];
    const float* wih_f  = (const float*)d_in[2];
    const float* whh_f  = (const float*)d_in[3];
    const float* bih_f  = (const float*)d_in[4];
    const float* bhh_f  = (const float*)d_in[5];
    const float* wih_b  = (const float*)d_in[6];
    const float* whh_b  = (const float*)d_in[7];
    const float* bih_b  = (const float*)d_in[8];
    const float* bhh_b  = (const float*)d_in[9];
    const float* attn_w = (const float*)d_in[10];
    const float* attn_b = (const float*)d_in[11];
    const float* comb_w = (const float*)d_in[12];
    const float* comb_b = (const float*)d_in[13];
    const float* fc_w   = (const float*)d_in[14];
    const float* fc_b   = (const float*)d_in[15];
    float* out = (float*)d_out;

    embed_kernel<<<BT, 256>>>(x, emb);
    xgemm_kernel<<<dim3(100, 8, 2), 256>>>(wih_f, wih_b, bih_f, bih_b);
    gru_kernel<<<dim3(32, 2), 128>>>(whh_f, whh_b, bhh_f, bhh_b);
    attn_kernel<<<32, 256>>>(attn_w, attn_b);
    comb_kernel<<<dim3(32, 8), 256>>>(comb_w, comb_b);
    logits_kernel<<<125, 256>>>(fc_w, fc_b, out);
}

// round 7
// speedup vs baseline: 1.7638x; 1.7638x over previous
#include <cuda_runtime.h>

#define B   32
#define T   100
#define V   10000
#define D   128
#define OUTN 1000
#define BT  (B*T)

typedef unsigned long long u64;

// ---------------- scratch (no allocations allowed) ----------------
__device__ float d_e[BT * D];          // embedded visits [B*T][128]
__device__ int   d_mask[BT];           // visit mask
__device__ float d_x3[BT * 768];       // input-side gates, [bt][dir*384 + g]
__device__ float d_hs[2 * BT * D];     // GRU outputs, dir-major
__device__ float d_ctx[B * 512];       // [c(256) | h_last(256)] per batch
__device__ float d_feat[B * D];        // combined feature

// ---------------- helpers ----------------
__device__ __forceinline__ u64 ffma2(u64 a, u64 b, u64 c) {
    u64 d;
    asm("fma.rn.f32x2 %0, %1, %2, %3;" : "=l"(d) : "l"(a), "l"(b), "l"(c));
    return d;
}
__device__ __forceinline__ float2 u2f2(u64 a) {
    float2 f;
    asm("mov.b64 {%0, %1}, %2;" : "=f"(f.x), "=f"(f.y) : "l"(a));
    return f;
}
__device__ __forceinline__ float fast_sigmoid(float x) {
    return 1.0f / (1.0f + __expf(-x));
}
__device__ __forceinline__ float fast_tanh(float x) {
    return 2.0f / (1.0f + __expf(-2.0f * x)) - 1.0f;
}

// ---------------- 1) sparse embedding + mask ----------------
__global__ void embed_kernel(const float* __restrict__ x, const float* __restrict__ emb) {
    int bt = blockIdx.x;
    __shared__ int cnt;
    __shared__ int idx[1024];
    __shared__ float part[128];
    if (threadIdx.x == 0) cnt = 0;
    __syncthreads();

    const float4* row = reinterpret_cast<const float4*>(x + (size_t)bt * V);
    for (int i = threadIdx.x; i < V / 4; i += blockDim.x) {
        float4 v = row[i];
        if (v.x != 0.f) { int p = atomicAdd(&cnt, 1); if (p < 1024) idx[p] = 4 * i; }
        if (v.y != 0.f) { int p = atomicAdd(&cnt, 1); if (p < 1024) idx[p] = 4 * i + 1; }
        if (v.z != 0.f) { int p = atomicAdd(&cnt, 1); if (p < 1024) idx[p] = 4 * i + 2; }
        if (v.w != 0.f) { int p = atomicAdd(&cnt, 1); if (p < 1024) idx[p] = 4 * i + 3; }
    }
    __syncthreads();
    int n = min(cnt, 1024);
    int d = threadIdx.x & 127;
    int half = threadIdx.x >> 7;
    float acc = 0.f;
    for (int j = half; j < n; j += 2) acc += emb[(size_t)idx[j] * D + d];
    if (half) part[d] = acc;
    __syncthreads();
    float tot = 0.f;
    if (half == 0) {
        tot = acc + part[d];
        d_e[bt * D + d] = tot;
    }
    int nz = __syncthreads_or(half == 0 && tot != 0.f);
    if (threadIdx.x == 0) d_mask[bt] = nz ? 1 : 0;
}

// ---------------- 2) x3 = e @ wih^T + bih, both dirs ----------------
// grid (100, 8, 2), 256 threads. tile: 32 bt-rows x 48 gate-cols, K=128.
#define ES 132  // padded row stride, 16B-aligned for LDS.128
__global__ void xgemm_kernel(const float* __restrict__ wih_f, const float* __restrict__ wih_b,
                             const float* __restrict__ bih_f, const float* __restrict__ bih_b) {
    const int bt0  = blockIdx.x * 32;
    const int col0 = blockIdx.y * 48;
    const int dir  = blockIdx.z;
    const float* W  = dir ? wih_b : wih_f;
    const float* bi = dir ? bih_b : bih_f;

    __shared__ __align__(16) float e_sh[32 * ES];
    __shared__ __align__(16) float w_sh[48 * ES];
    int tid = threadIdx.x;
    for (int i = tid; i < 32 * 32; i += 256) {          // float4 granularity
        int r = i >> 5, k4 = i & 31;
        *reinterpret_cast<float4*>(&e_sh[r * ES + 4 * k4]) =
            *reinterpret_cast<const float4*>(&d_e[(bt0 + r) * D + 4 * k4]);
    }
    for (int i = tid; i < 48 * 32; i += 256) {
        int c = i >> 5, k4 = i & 31;
        *reinterpret_cast<float4*>(&w_sh[c * ES + 4 * k4]) =
            *reinterpret_cast<const float4*>(&W[(size_t)(col0 + c) * D + 4 * k4]);
    }
    __syncthreads();

    int rt = tid & 15;   // rows 2*rt, 2*rt+1
    int ct = tid >> 4;   // cols 3*ct .. 3*ct+2
    int r0 = rt * 2, c0 = ct * 3;

    u64 accP[2][3] = {}, accQ[2][3] = {};
    for (int k = 0; k < 128; k += 4) {
        ulonglong2 ev[2], wv[3];
#pragma unroll
        for (int i = 0; i < 2; i++)
            ev[i] = *reinterpret_cast<const ulonglong2*>(&e_sh[(r0 + i) * ES + k]);
#pragma unroll
        for (int c = 0; c < 3; c++)
            wv[c] = *reinterpret_cast<const ulonglong2*>(&w_sh[(c0 + c) * ES + k]);
#pragma unroll
        for (int i = 0; i < 2; i++)
#pragma unroll
            for (int c = 0; c < 3; c++) {
                accP[i][c] = ffma2(ev[i].x, wv[c].x, accP[i][c]);
                accQ[i][c] = ffma2(ev[i].y, wv[c].y, accQ[i][c]);
            }
    }
#pragma unroll
    for (int i = 0; i < 2; i++)
#pragma unroll
        for (int c = 0; c < 3; c++) {
            float2 p = u2f2(accP[i][c]), q = u2f2(accQ[i][c]);
            float v = (p.x + p.y) + (q.x + q.y) + bi[col0 + c0 + c];
            d_x3[(size_t)(bt0 + r0 + i) * 768 + dir * 384 + col0 + c0 + c] = v;
        }
}

// ---------------- 3) GRU, one CTA per (batch, dir) ----------------
// R3-proven structure: 384 threads, thread j owns whh row j in registers
// (64 u64 = 128 regs, fits the 170-reg budget at 384 thr). LDS.128 broadcast
// h loads, prefetched x, 2 barriers/step.
__global__ void __launch_bounds__(384, 1)
gru_kernel(const float* __restrict__ whh_f, const float* __restrict__ whh_b,
           const float* __restrict__ bhh_f, const float* __restrict__ bhh_b) {
    int b = blockIdx.x, dir = blockIdx.y;
    int j = threadIdx.x;
    const float* whh = dir ? whh_b : whh_f;

    __shared__ __align__(16) float h_f[128];
    __shared__ float gh_sh[384];

    u64 wr[64];
    const u64* wrow = reinterpret_cast<const u64*>(whh + (size_t)j * 128);
#pragma unroll
    for (int k = 0; k < 64; k++) wr[k] = wrow[k];
    float bh = (dir ? bhh_b : bhh_f)[j];
    if (j < 128) h_f[j] = 0.f;

    const float* x3p = d_x3 + (size_t)b * T * 768 + dir * 384
                       + (dir ? (size_t)(T - 1) * 768 : 0);
    const long xstep = dir ? -768 : 768;
    float* hsp = d_hs + ((size_t)dir * BT + (size_t)b * T) * D
                 + (dir ? (size_t)(T - 1) * D : 0) + (j & 127);
    const long hstep = dir ? -(long)D : (long)D;

    float xr = 0.f, xz = 0.f, xn = 0.f;
    if (j < 128) { xr = x3p[j]; xz = x3p[128 + j]; xn = x3p[256 + j]; }
    __syncthreads();

    const ulonglong2* hv2 = reinterpret_cast<const ulonglong2*>(h_f);

    for (int s = 0; s < T; s++) {
        u64 a0 = 0, a1 = 0, a2 = 0, a3 = 0;
#pragma unroll
        for (int k = 0; k < 32; k += 2) {
            ulonglong2 h0 = hv2[k];
            ulonglong2 h1 = hv2[k + 1];
            a0 = ffma2(wr[2 * k],     h0.x, a0);
            a1 = ffma2(wr[2 * k + 1], h0.y, a1);
            a2 = ffma2(wr[2 * k + 2], h1.x, a2);
            a3 = ffma2(wr[2 * k + 3], h1.y, a3);
        }
        float2 f0 = u2f2(a0), f1 = u2f2(a1), f2 = u2f2(a2), f3 = u2f2(a3);
        gh_sh[j] = ((f0.x + f0.y) + (f1.x + f1.y)) + ((f2.x + f2.y) + (f3.x + f3.y)) + bh;
        __syncthreads();

        if (j < 128) {
            float r = fast_sigmoid(xr + gh_sh[j]);
            float z = fast_sigmoid(xz + gh_sh[128 + j]);
            float n = fast_tanh(xn + r * gh_sh[256 + j]);
            float hnew = (1.f - z) * n + z * h_f[j];
            h_f[j] = hnew;
            *hsp = hnew;
            if (s + 1 < T) {
                const float* xp = x3p + xstep;
                xr = xp[j]; xz = xp[128 + j]; xn = xp[256 + j];
            }
        }
        hsp += hstep;
        x3p += xstep;
        __syncthreads();
    }
}

// ---------------- 4a) attention: scores, softmax, context, h_last ----------------
__global__ void attn_kernel(const float* __restrict__ aw, const float* __restrict__ ab) {
    int b = blockIdx.x;
    int tid = threadIdx.x;  // 256
    __shared__ float aw_sh[256];
    __shared__ float sc[128];
    __shared__ int   msk[128];
    __shared__ int last_sh;

    aw_sh[tid] = aw[tid];
    if (tid < T) msk[tid] = d_mask[b * T + tid];
    __syncthreads();

    const float* hf = d_hs + (size_t)b * T * D;
    const float* hb = d_hs + ((size_t)BT + (size_t)b * T) * D;
    int w = tid >> 5, lane = tid & 31;

    for (int t = w; t < T; t += 8) {
        float s = 0.f;
        const float* pf = hf + (size_t)t * D;
        const float* pb = hb + (size_t)t * D;
#pragma unroll
        for (int d = lane; d < D; d += 32)
            s += pf[d] * aw_sh[d] + pb[d] * aw_sh[128 + d];
#pragma unroll
        for (int o = 16; o; o >>= 1) s += __shfl_xor_sync(0xffffffffu, s, o);
        if (lane == 0) sc[t] = msk[t] ? (s + ab[0]) : -1e9f;
    }
    __syncthreads();

    if (w == 0) {
        float m = -1e30f;
        for (int t = lane; t < T; t += 32) m = fmaxf(m, sc[t]);
#pragma unroll
        for (int o = 16; o; o >>= 1) m = fmaxf(m, __shfl_xor_sync(0xffffffffu, m, o));
        float s = 0.f;
        for (int t = lane; t < T; t += 32) { float e = __expf(sc[t] - m); sc[t] = e; s += e; }
#pragma unroll
        for (int o = 16; o; o >>= 1) s += __shfl_xor_sync(0xffffffffu, s, o);
        float inv = 1.f / s;
        for (int t = lane; t < T; t += 32) sc[t] *= inv;
        int c = 0;
        for (int t = lane; t < T; t += 32) c += msk[t];
#pragma unroll
        for (int o = 16; o; o >>= 1) c += __shfl_xor_sync(0xffffffffu, c, o);
        if (lane == 0) last_sh = c - 1;
    }
    __syncthreads();

    int last = last_sh;
    int f = tid;
    const float* hcol = (f < 128) ? (hf + f) : (hb + (f - 128));
    float cacc = 0.f;
#pragma unroll
    for (int t0 = 0; t0 < T; t0 += 10) {
        float p = 0.f;
#pragma unroll
        for (int u = 0; u < 10; u++)
            p += sc[t0 + u] * hcol[(size_t)(t0 + u) * D];
        cacc += p;
    }
    d_ctx[b * 512 + f] = cacc;
    d_ctx[b * 512 + 256 + f] = hcol[(size_t)last * D];
}

// ---------------- 4b) combine: feat = tanh(ctx @ comb_w^T + comb_b) ----------------
// grid (32, 8), 256 threads; CTA handles 16 outputs for one batch (2 per warp).
__global__ void comb_kernel(const float* __restrict__ comb_w, const float* __restrict__ comb_b) {
    int b = blockIdx.x, og = blockIdx.y;
    int tid = threadIdx.x, w = tid >> 5, lane = tid & 31;
    __shared__ __align__(16) float ctx[512];
    ctx[tid] = d_ctx[b * 512 + tid];
    ctx[256 + tid] = d_ctx[b * 512 + 256 + tid];
    __syncthreads();

    int o = og * 16 + 2 * w;
    const float4* rowA = reinterpret_cast<const float4*>(comb_w + (size_t)o * 512);
    const float4* rowB = reinterpret_cast<const float4*>(comb_w + (size_t)(o + 1) * 512);
    float accA = 0.f, accB = 0.f;
#pragma unroll
    for (int q = 0; q < 4; q++) {
        int i = lane + 32 * q;
        float4 wa = rowA[i];
        float4 wb = rowB[i];
        float4 iv = *reinterpret_cast<const float4*>(&ctx[4 * i]);
        accA += wa.x * iv.x + wa.y * iv.y + wa.z * iv.z + wa.w * iv.w;
        accB += wb.x * iv.x + wb.y * iv.y + wb.z * iv.z + wb.w * iv.w;
    }
#pragma unroll
    for (int of = 16; of; of >>= 1) {
        accA += __shfl_xor_sync(0xffffffffu, accA, of);
        accB += __shfl_xor_sync(0xffffffffu, accB, of);
    }
    if (lane == 0) {
        d_feat[b * D + o]     = fast_tanh(accA + comb_b[o]);
        d_feat[b * D + o + 1] = fast_tanh(accB + comb_b[o + 1]);
    }
}

// ---------------- 5) logits = feat @ fc_w^T + fc_b ----------------
#define FS 132
__global__ void logits_kernel(const float* __restrict__ fc_w, const float* __restrict__ fc_b,
                              float* __restrict__ out) {
    int o0 = blockIdx.x * 8;
    int tid = threadIdx.x;
    __shared__ __align__(16) float fsh[32 * FS];
    __shared__ __align__(16) float wsh[8 * 128];
    for (int i = tid; i < 32 * 32; i += 256) {
        int bb = i >> 5, k4 = i & 31;
        *reinterpret_cast<float4*>(&fsh[bb * FS + 4 * k4]) =
            *reinterpret_cast<const float4*>(&d_feat[bb * D + 4 * k4]);
    }
    for (int i = tid; i < 8 * 32; i += 256)
        *reinterpret_cast<float4*>(&wsh[4 * i]) =
            *reinterpret_cast<const float4*>(&fc_w[(size_t)o0 * 128 + 4 * i]);
    __syncthreads();

    int bb = tid & 31, oj = tid >> 5;
    float acc = fc_b[o0 + oj];
#pragma unroll
    for (int k = 0; k < 128; k += 4) {
        float4 fv = *reinterpret_cast<const float4*>(&fsh[bb * FS + k]);
        float4 wv = *reinterpret_cast<const float4*>(&wsh[oj * 128 + k]);
        acc += fv.x * wv.x + fv.y * wv.y + fv.z * wv.z + fv.w * wv.w;
    }
    out[(size_t)bb * OUTN + o0 + oj] = acc;
}

// ---------------- launch ----------------
extern "C" void kernel_launch(void* const* d_in, const int* in_sizes, int n_in,
                              void* d_out, int out_size) {
    const float* x      = (const float*)d_in[0];
    const float* emb    = (const float*)d_in[1];
    const float* wih_f  = (const float*)d_in[2];
    const float* whh_f  = (const float*)d_in[3];
    const float* bih_f  = (const float*)d_in[4];
    const float* bhh_f  = (const float*)d_in[5];
    const float* wih_b  = (const float*)d_in[6];
    const float* whh_b  = (const float*)d_in[7];
    const float* bih_b  = (const float*)d_in[8];
    const float* bhh_b  = (const float*)d_in[9];
    const float* attn_w = (const float*)d_in[10];
    const float* attn_b = (const float*)d_in[11];
    const float* comb_w = (const float*)d_in[12];
    const float* comb_b = (const float*)d_in[13];
    const float* fc_w   = (const float*)d_in[14];
    const float* fc_b   = (const float*)d_in[15];
    float* out = (float*)d_out;

    embed_kernel<<<BT, 256>>>(x, emb);
    xgemm_kernel<<<dim3(100, 8, 2), 256>>>(wih_f, wih_b, bih_f, bih_b);
    gru_kernel<<<dim3(32, 2), 384>>>(whh_f, whh_b, bhh_f, bhh_b);
    attn_kernel<<<32, 256>>>(attn_w, attn_b);
    comb_kernel<<<dim3(32, 8), 256>>>(comb_w, comb_b);
    logits_kernel<<<125, 256>>>(fc_w, fc_b, out);
}

// round 8
// speedup vs baseline: 2.0072x; 1.1380x over previous
#include <cuda_runtime.h>

#define B   32
#define T   100
#define V   10000
#define D   128
#define OUTN 1000
#define BT  (B*T)

typedef unsigned long long u64;

// ---------------- scratch (no allocations allowed) ----------------
__device__ float d_e[BT * D];          // embedded visits [B*T][128]
__device__ int   d_mask[BT];           // visit mask
__device__ float d_x3[BT * 768];       // input-side gates, [bt][dir*384 + g]
__device__ float d_hs[2 * BT * D];     // GRU outputs, dir-major
__device__ float d_attnw[B * 128];     // softmax attention weights
__device__ int   d_last[B];            // last valid visit index
__device__ float d_ctx[B * 512];       // [c(256) | h_last(256)] per batch
__device__ float d_feat[B * D];        // combined feature

// ---------------- helpers ----------------
__device__ __forceinline__ u64 ffma2(u64 a, u64 b, u64 c) {
    u64 d;
    asm("fma.rn.f32x2 %0, %1, %2, %3;" : "=l"(d) : "l"(a), "l"(b), "l"(c));
    return d;
}
__device__ __forceinline__ float2 u2f2(u64 a) {
    float2 f;
    asm("mov.b64 {%0, %1}, %2;" : "=f"(f.x), "=f"(f.y) : "l"(a));
    return f;
}
__device__ __forceinline__ float tanh_ap(float x) {
    float y;
    asm("tanh.approx.f32 %0, %1;" : "=f"(y) : "f"(x));
    return y;
}
__device__ __forceinline__ float sigmoid_ap(float x) {
    return 0.5f * tanh_ap(0.5f * x) + 0.5f;
}

// ---------------- 1) sparse embedding + mask ----------------
// grid = BT blocks, 512 threads; fully-unrolled streaming scan of x.
__global__ void __launch_bounds__(512, 1)
embed_kernel(const float* __restrict__ x, const float* __restrict__ emb) {
    int bt = blockIdx.x;
    __shared__ int cnt;
    __shared__ int idx[1024];
    __shared__ float part[3][128];
    if (threadIdx.x == 0) cnt = 0;
    __syncthreads();

    const float4* row = reinterpret_cast<const float4*>(x + (size_t)bt * V);
    {
        float4 v[5];
        int base = threadIdx.x;
#pragma unroll
        for (int k = 0; k < 5; k++) {
            int i = base + k * 512;
            if (i < V / 4) v[k] = __ldcs(&row[i]);
            else v[k] = make_float4(0.f, 0.f, 0.f, 0.f);
        }
#pragma unroll
        for (int k = 0; k < 5; k++) {
            int i = base + k * 512;
            if (v[k].x != 0.f) { int p = atomicAdd(&cnt, 1); if (p < 1024) idx[p] = 4 * i; }
            if (v[k].y != 0.f) { int p = atomicAdd(&cnt, 1); if (p < 1024) idx[p] = 4 * i + 1; }
            if (v[k].z != 0.f) { int p = atomicAdd(&cnt, 1); if (p < 1024) idx[p] = 4 * i + 2; }
            if (v[k].w != 0.f) { int p = atomicAdd(&cnt, 1); if (p < 1024) idx[p] = 4 * i + 3; }
        }
    }
    __syncthreads();
    int n = min(cnt, 1024);
    int d = threadIdx.x & 127;
    int quarter = threadIdx.x >> 7;
    float acc = 0.f;
    for (int j = quarter; j < n; j += 4) acc += emb[(size_t)idx[j] * D + d];
    if (quarter) part[quarter - 1][d] = acc;
    __syncthreads();
    float tot = 0.f;
    if (quarter == 0) {
        tot = acc + part[0][d] + part[1][d] + part[2][d];
        d_e[bt * D + d] = tot;
    }
    int nz = __syncthreads_or(quarter == 0 && tot != 0.f);
    if (threadIdx.x == 0) d_mask[bt] = nz ? 1 : 0;
}

// ---------------- 2) x3 = e @ wih^T + bih, both dirs ----------------
// grid (100, 8, 2), 256 threads. tile: 32 bt-rows x 48 gate-cols, K=128.
#define ES 132  // padded row stride, 16B-aligned for LDS.128
__global__ void xgemm_kernel(const float* __restrict__ wih_f, const float* __restrict__ wih_b,
                             const float* __restrict__ bih_f, const float* __restrict__ bih_b) {
    const int bt0  = blockIdx.x * 32;
    const int col0 = blockIdx.y * 48;
    const int dir  = blockIdx.z;
    const float* W  = dir ? wih_b : wih_f;
    const float* bi = dir ? bih_b : bih_f;

    __shared__ __align__(16) float e_sh[32 * ES];
    __shared__ __align__(16) float w_sh[48 * ES];
    int tid = threadIdx.x;
    for (int i = tid; i < 32 * 32; i += 256) {
        int r = i >> 5, k4 = i & 31;
        *reinterpret_cast<float4*>(&e_sh[r * ES + 4 * k4]) =
            *reinterpret_cast<const float4*>(&d_e[(bt0 + r) * D + 4 * k4]);
    }
    for (int i = tid; i < 48 * 32; i += 256) {
        int c = i >> 5, k4 = i & 31;
        *reinterpret_cast<float4*>(&w_sh[c * ES + 4 * k4]) =
            *reinterpret_cast<const float4*>(&W[(size_t)(col0 + c) * D + 4 * k4]);
    }
    __syncthreads();

    int rt = tid & 15;
    int ct = tid >> 4;
    int r0 = rt * 2, c0 = ct * 3;

    u64 accP[2][3] = {}, accQ[2][3] = {};
    for (int k = 0; k < 128; k += 4) {
        ulonglong2 ev[2], wv[3];
#pragma unroll
        for (int i = 0; i < 2; i++)
            ev[i] = *reinterpret_cast<const ulonglong2*>(&e_sh[(r0 + i) * ES + k]);
#pragma unroll
        for (int c = 0; c < 3; c++)
            wv[c] = *reinterpret_cast<const ulonglong2*>(&w_sh[(c0 + c) * ES + k]);
#pragma unroll
        for (int i = 0; i < 2; i++)
#pragma unroll
            for (int c = 0; c < 3; c++) {
                accP[i][c] = ffma2(ev[i].x, wv[c].x, accP[i][c]);
                accQ[i][c] = ffma2(ev[i].y, wv[c].y, accQ[i][c]);
            }
    }
#pragma unroll
    for (int i = 0; i < 2; i++)
#pragma unroll
        for (int c = 0; c < 3; c++) {
            float2 p = u2f2(accP[i][c]), q = u2f2(accQ[i][c]);
            float v = (p.x + p.y) + (q.x + q.y) + bi[col0 + c0 + c];
            d_x3[(size_t)(bt0 + r0 + i) * 768 + dir * 384 + col0 + c0 + c] = v;
        }
}

// ---------------- 3) GRU, one CTA per (batch, dir) ----------------
// 384 threads, thread j owns whh row j in registers (64 u64 = 128 regs).
__global__ void __launch_bounds__(384, 1)
gru_kernel(const float* __restrict__ whh_f, const float* __restrict__ whh_b,
           const float* __restrict__ bhh_f, const float* __restrict__ bhh_b) {
    int b = blockIdx.x, dir = blockIdx.y;
    int j = threadIdx.x;
    const float* whh = dir ? whh_b : whh_f;

    __shared__ __align__(16) float h_f[128];
    __shared__ float gh_sh[384];

    u64 wr[64];
    const u64* wrow = reinterpret_cast<const u64*>(whh + (size_t)j * 128);
#pragma unroll
    for (int k = 0; k < 64; k++) wr[k] = wrow[k];
    float bh = (dir ? bhh_b : bhh_f)[j];
    if (j < 128) h_f[j] = 0.f;

    const float* x3p = d_x3 + (size_t)b * T * 768 + dir * 384
                       + (dir ? (size_t)(T - 1) * 768 : 0);
    const long xstep = dir ? -768 : 768;
    float* hsp = d_hs + ((size_t)dir * BT + (size_t)b * T) * D
                 + (dir ? (size_t)(T - 1) * D : 0) + (j & 127);
    const long hstep = dir ? -(long)D : (long)D;

    float xr = 0.f, xz = 0.f, xn = 0.f;
    if (j < 128) { xr = x3p[j]; xz = x3p[128 + j]; xn = x3p[256 + j]; }
    __syncthreads();

    const ulonglong2* hv2 = reinterpret_cast<const ulonglong2*>(h_f);

    for (int s = 0; s < T; s++) {
        u64 a0 = 0, a1 = 0, a2 = 0, a3 = 0;
#pragma unroll
        for (int k = 0; k < 32; k += 2) {
            ulonglong2 h0 = hv2[k];
            ulonglong2 h1 = hv2[k + 1];
            a0 = ffma2(wr[2 * k],     h0.x, a0);
            a1 = ffma2(wr[2 * k + 1], h0.y, a1);
            a2 = ffma2(wr[2 * k + 2], h1.x, a2);
            a3 = ffma2(wr[2 * k + 3], h1.y, a3);
        }
        float2 f0 = u2f2(a0), f1 = u2f2(a1), f2 = u2f2(a2), f3 = u2f2(a3);
        gh_sh[j] = ((f0.x + f0.y) + (f1.x + f1.y)) + ((f2.x + f2.y) + (f3.x + f3.y)) + bh;
        __syncthreads();

        if (j < 128) {
            float r = sigmoid_ap(xr + gh_sh[j]);
            float z = sigmoid_ap(xz + gh_sh[128 + j]);
            float n = tanh_ap(xn + r * gh_sh[256 + j]);
            float hnew = (1.f - z) * n + z * h_f[j];
            h_f[j] = hnew;
            *hsp = hnew;
            if (s + 1 < T) {
                const float* xp = x3p + xstep;
                xr = xp[j]; xz = xp[128 + j]; xn = xp[256 + j];
            }
        }
        hsp += hstep;
        x3p += xstep;
        __syncthreads();
    }
}

// ---------------- 4a) attention scores + softmax + last ----------------
__global__ void attn1_kernel(const float* __restrict__ aw, const float* __restrict__ ab) {
    int b = blockIdx.x;
    int tid = threadIdx.x;  // 256
    __shared__ float aw_sh[256];
    __shared__ float sc[128];
    __shared__ int   msk[128];

    aw_sh[tid] = aw[tid];
    if (tid < T) msk[tid] = d_mask[b * T + tid];
    __syncthreads();

    const float* hf = d_hs + (size_t)b * T * D;
    const float* hb = d_hs + ((size_t)BT + (size_t)b * T) * D;
    int w = tid >> 5, lane = tid & 31;

    for (int t = w; t < T; t += 8) {
        float s = 0.f;
        const float* pf = hf + (size_t)t * D;
        const float* pb = hb + (size_t)t * D;
#pragma unroll
        for (int d = lane; d < D; d += 32)
            s += pf[d] * aw_sh[d] + pb[d] * aw_sh[128 + d];
#pragma unroll
        for (int o = 16; o; o >>= 1) s += __shfl_xor_sync(0xffffffffu, s, o);
        if (lane == 0) sc[t] = msk[t] ? (s + ab[0]) : -1e9f;
    }
    __syncthreads();

    if (w == 0) {
        float m = -1e30f;
        for (int t = lane; t < T; t += 32) m = fmaxf(m, sc[t]);
#pragma unroll
        for (int o = 16; o; o >>= 1) m = fmaxf(m, __shfl_xor_sync(0xffffffffu, m, o));
        float s = 0.f;
        for (int t = lane; t < T; t += 32) { float e = __expf(sc[t] - m); sc[t] = e; s += e; }
#pragma unroll
        for (int o = 16; o; o >>= 1) s += __shfl_xor_sync(0xffffffffu, s, o);
        float inv = 1.f / s;
        for (int t = lane; t < T; t += 32) d_attnw[b * 128 + t] = sc[t] * inv;
        int c = 0;
        for (int t = lane; t < T; t += 32) c += msk[t];
#pragma unroll
        for (int o = 16; o; o >>= 1) c += __shfl_xor_sync(0xffffffffu, c, o);
        if (lane == 0) d_last[b] = c - 1;
    }
}

// ---------------- 4b) context + h_last, grid (32, 2), 128 threads ----------------
__global__ void attn2_kernel() {
    int b = blockIdx.x, dir = blockIdx.y;
    int f = threadIdx.x;  // 128
    __shared__ float a_sh[128];
    if (f < T) a_sh[f] = d_attnw[b * 128 + f];
    __syncthreads();
    int last = d_last[b];

    const float* hcol = d_hs + ((size_t)dir * BT + (size_t)b * T) * D + f;
    float cacc = 0.f;
#pragma unroll
    for (int t0 = 0; t0 < T; t0 += 10) {
        float p = 0.f;
#pragma unroll
        for (int u = 0; u < 10; u++)
            p += a_sh[t0 + u] * hcol[(size_t)(t0 + u) * D];
        cacc += p;
    }
    d_ctx[b * 512 + dir * 128 + f] = cacc;
    d_ctx[b * 512 + 256 + dir * 128 + f] = hcol[(size_t)last * D];
}

// ---------------- 4c) combine: feat = tanh(ctx @ comb_w^T + comb_b) ----------------
// grid (32, 8), 256 threads; CTA handles 16 outputs for one batch (2 per warp).
__global__ void comb_kernel(const float* __restrict__ comb_w, const float* __restrict__ comb_b) {
    int b = blockIdx.x, og = blockIdx.y;
    int tid = threadIdx.x, w = tid >> 5, lane = tid & 31;
    __shared__ __align__(16) float ctx[512];
    ctx[tid] = d_ctx[b * 512 + tid];
    ctx[256 + tid] = d_ctx[b * 512 + 256 + tid];
    __syncthreads();

    int o = og * 16 + 2 * w;
    const float4* rowA = reinterpret_cast<const float4*>(comb_w + (size_t)o * 512);
    const float4* rowB = reinterpret_cast<const float4*>(comb_w + (size_t)(o + 1) * 512);
    float accA = 0.f, accB = 0.f;
#pragma unroll
    for (int q = 0; q < 4; q++) {
        int i = lane + 32 * q;
        float4 wa = __ldcs(&rowA[i]);
        float4 wb = __ldcs(&rowB[i]);
        float4 iv = *reinterpret_cast<const float4*>(&ctx[4 * i]);
        accA += wa.x * iv.x + wa.y * iv.y + wa.z * iv.z + wa.w * iv.w;
        accB += wb.x * iv.x + wb.y * iv.y + wb.z * iv.z + wb.w * iv.w;
    }
#pragma unroll
    for (int of = 16; of; of >>= 1) {
        accA += __shfl_xor_sync(0xffffffffu, accA, of);
        accB += __shfl_xor_sync(0xffffffffu, accB, of);
    }
    if (lane == 0) {
        d_feat[b * D + o]     = tanh_ap(accA + comb_b[o]);
        d_feat[b * D + o + 1] = tanh_ap(accB + comb_b[o + 1]);
    }
}

// ---------------- 5) logits = feat @ fc_w^T + fc_b ----------------
#define FS 132
__global__ void logits_kernel(const float* __restrict__ fc_w, const float* __restrict__ fc_b,
                              float* __restrict__ out) {
    int o0 = blockIdx.x * 8;
    int tid = threadIdx.x;
    __shared__ __align__(16) float fsh[32 * FS];
    __shared__ __align__(16) float wsh[8 * 128];
    for (int i = tid; i < 32 * 32; i += 256) {
        int bb = i >> 5, k4 = i & 31;
        *reinterpret_cast<float4*>(&fsh[bb * FS + 4 * k4]) =
            *reinterpret_cast<const float4*>(&d_feat[bb * D + 4 * k4]);
    }
    for (int i = tid; i < 8 * 32; i += 256)
        *reinterpret_cast<float4*>(&wsh[4 * i]) =
            __ldcs(reinterpret_cast<const float4*>(&fc_w[(size_t)o0 * 128 + 4 * i]));
    __syncthreads();

    int bb = tid & 31, oj = tid >> 5;
    float acc = fc_b[o0 + oj];
#pragma unroll
    for (int k = 0; k < 128; k += 4) {
        float4 fv = *reinterpret_cast<const float4*>(&fsh[bb * FS + k]);
        float4 wv = *reinterpret_cast<const float4*>(&wsh[oj * 128 + k]);
        acc += fv.x * wv.x + fv.y * wv.y + fv.z * wv.z + fv.w * wv.w;
    }
    out[(size_t)bb * OUTN + o0 + oj] = acc;
}

// ---------------- launch ----------------
extern "C" void kernel_launch(void* const* d_in, const int* in_sizes, int n_in,
                              void* d_out, int out_size) {
    const float* x      = (const float*)d_in[0];
    const float* emb    = (const float*)d_in[1];
    const float* wih_f  = (const float*)d_in[2];
    const float* whh_f  = (const float*)d_in[3];
    const float* bih_f  = (const float*)d_in[4];
    const float* bhh_f  = (const float*)d_in[5];
    const float* wih_b  = (const float*)d_in[6];
    const float* whh_b  = (const float*)d_in[7];
    const float* bih_b  = (const float*)d_in[8];
    const float* bhh_b  = (const float*)d_in[9];
    const float* attn_w = (const float*)d_in[10];
    const float* attn_b = (const float*)d_in[11];
    const float* comb_w = (const float*)d_in[12];
    const float* comb_b = (const float*)d_in[13];
    const float* fc_w   = (const float*)d_in[14];
    const float* fc_b   = (const float*)d_in[15];
    float* out = (float*)d_out;

    embed_kernel<<<BT, 512>>>(x, emb);
    xgemm_kernel<<<dim3(100, 8, 2), 256>>>(wih_f, wih_b, bih_f, bih_b);
    gru_kernel<<<dim3(32, 2), 384>>>(whh_f, whh_b, bhh_f, bhh_b);
    attn1_kernel<<<32, 256>>>(attn_w, attn_b);
    attn2_kernel<<<dim3(32, 2), 128>>>();
    comb_kernel<<<dim3(32, 8), 256>>>(comb_w, comb_b);
    logits_kernel<<<125, 256>>>(fc_w, fc_b, out);
}

// round 9
// speedup vs baseline: 2.1118x; 1.0521x over previous
#include <cuda_runtime.h>

#define B   32
#define T   100
#define V   10000
#define D   128
#define OUTN 1000
#define BT  (B*T)

typedef unsigned long long u64;

// ---------------- scratch (no allocations allowed) ----------------
__device__ float d_e[BT * D];          // embedded visits [B*T][128]
__device__ int   d_mask[BT];           // visit mask
__device__ float d_x3[BT * 768];       // input-side gates, [bt][dir*384 + g]
__device__ float d_hs[2 * BT * D];     // GRU outputs, dir-major
__device__ float d_attnw[B * 128];     // softmax attention weights
__device__ int   d_last[B];            // last valid visit index
__device__ float d_ctx[B * 512];       // [c(256) | h_last(256)] per batch
__device__ float d_feat[B * D];        // combined feature

// ---------------- helpers ----------------
__device__ __forceinline__ u64 ffma2(u64 a, u64 b, u64 c) {
    u64 d;
    asm("fma.rn.f32x2 %0, %1, %2, %3;" : "=l"(d) : "l"(a), "l"(b), "l"(c));
    return d;
}
__device__ __forceinline__ float2 u2f2(u64 a) {
    float2 f;
    asm("mov.b64 {%0, %1}, %2;" : "=f"(f.x), "=f"(f.y) : "l"(a));
    return f;
}
__device__ __forceinline__ float tanh_ap(float x) {
    float y;
    asm("tanh.approx.f32 %0, %1;" : "=f"(y) : "f"(x));
    return y;
}
__device__ __forceinline__ float sigmoid_ap(float x) {
    return 0.5f * tanh_ap(0.5f * x) + 0.5f;
}

// ---------------- 1) sparse embedding + mask ----------------
__global__ void __launch_bounds__(512, 1)
embed_kernel(const float* __restrict__ x, const float* __restrict__ emb) {
    int bt = blockIdx.x;
    __shared__ int cnt;
    __shared__ int idx[1024];
    __shared__ float part[3][128];
    if (threadIdx.x == 0) cnt = 0;
    __syncthreads();

    const float4* row = reinterpret_cast<const float4*>(x + (size_t)bt * V);
    {
        float4 v[5];
        int base = threadIdx.x;
#pragma unroll
        for (int k = 0; k < 5; k++) {
            int i = base + k * 512;
            if (i < V / 4) v[k] = __ldcs(&row[i]);
            else v[k] = make_float4(0.f, 0.f, 0.f, 0.f);
        }
#pragma unroll
        for (int k = 0; k < 5; k++) {
            int i = base + k * 512;
            if (v[k].x != 0.f) { int p = atomicAdd(&cnt, 1); if (p < 1024) idx[p] = 4 * i; }
            if (v[k].y != 0.f) { int p = atomicAdd(&cnt, 1); if (p < 1024) idx[p] = 4 * i + 1; }
            if (v[k].z != 0.f) { int p = atomicAdd(&cnt, 1); if (p < 1024) idx[p] = 4 * i + 2; }
            if (v[k].w != 0.f) { int p = atomicAdd(&cnt, 1); if (p < 1024) idx[p] = 4 * i + 3; }
        }
    }
    __syncthreads();
    int n = min(cnt, 1024);
    int d = threadIdx.x & 127;
    int quarter = threadIdx.x >> 7;
    float acc = 0.f;
    for (int j = quarter; j < n; j += 4) acc += emb[(size_t)idx[j] * D + d];
    if (quarter) part[quarter - 1][d] = acc;
    __syncthreads();
    float tot = 0.f;
    if (quarter == 0) {
        tot = acc + part[0][d] + part[1][d] + part[2][d];
        d_e[bt * D + d] = tot;
    }
    int nz = __syncthreads_or(quarter == 0 && tot != 0.f);
    if (threadIdx.x == 0) d_mask[bt] = nz ? 1 : 0;
}

// ---------------- 2) x3 = e @ wih^T + bih, both dirs ----------------
#define ES 132
__global__ void xgemm_kernel(const float* __restrict__ wih_f, const float* __restrict__ wih_b,
                             const float* __restrict__ bih_f, const float* __restrict__ bih_b) {
    const int bt0  = blockIdx.x * 32;
    const int col0 = blockIdx.y * 48;
    const int dir  = blockIdx.z;
    const float* W  = dir ? wih_b : wih_f;
    const float* bi = dir ? bih_b : bih_f;

    __shared__ __align__(16) float e_sh[32 * ES];
    __shared__ __align__(16) float w_sh[48 * ES];
    int tid = threadIdx.x;
    for (int i = tid; i < 32 * 32; i += 256) {
        int r = i >> 5, k4 = i & 31;
        *reinterpret_cast<float4*>(&e_sh[r * ES + 4 * k4]) =
            *reinterpret_cast<const float4*>(&d_e[(bt0 + r) * D + 4 * k4]);
    }
    for (int i = tid; i < 48 * 32; i += 256) {
        int c = i >> 5, k4 = i & 31;
        *reinterpret_cast<float4*>(&w_sh[c * ES + 4 * k4]) =
            *reinterpret_cast<const float4*>(&W[(size_t)(col0 + c) * D + 4 * k4]);
    }
    __syncthreads();

    int rt = tid & 15;
    int ct = tid >> 4;
    int r0 = rt * 2, c0 = ct * 3;

    u64 accP[2][3] = {}, accQ[2][3] = {};
    for (int k = 0; k < 128; k += 4) {
        ulonglong2 ev[2], wv[3];
#pragma unroll
        for (int i = 0; i < 2; i++)
            ev[i] = *reinterpret_cast<const ulonglong2*>(&e_sh[(r0 + i) * ES + k]);
#pragma unroll
        for (int c = 0; c < 3; c++)
            wv[c] = *reinterpret_cast<const ulonglong2*>(&w_sh[(c0 + c) * ES + k]);
#pragma unroll
        for (int i = 0; i < 2; i++)
#pragma unroll
            for (int c = 0; c < 3; c++) {
                accP[i][c] = ffma2(ev[i].x, wv[c].x, accP[i][c]);
                accQ[i][c] = ffma2(ev[i].y, wv[c].y, accQ[i][c]);
            }
    }
#pragma unroll
    for (int i = 0; i < 2; i++)
#pragma unroll
        for (int c = 0; c < 3; c++) {
            float2 p = u2f2(accP[i][c]), q = u2f2(accQ[i][c]);
            float v = (p.x + p.y) + (q.x + q.y) + bi[col0 + c0 + c];
            d_x3[(size_t)(bt0 + r0 + i) * 768 + dir * 384 + col0 + c0 + c] = v;
        }
}

// ---------------- 3) GRU, one CTA per (batch, dir) ----------------
// 256 threads. Lane pair (unit, tier): thread owns all 3 gate rows of its
// unit, K-half `tier` (96 u64 weight regs). Gate sums completed by one
// shfl_xor(1) inside the warp; activation in registers; ONE barrier/step.
__global__ void __launch_bounds__(256, 1)
gru_kernel(const float* __restrict__ whh_f, const float* __restrict__ whh_b,
           const float* __restrict__ bhh_f, const float* __restrict__ bhh_b) {
    int b = blockIdx.x, dir = blockIdx.y;
    int tid = threadIdx.x;
    int lane = tid & 31, warp = tid >> 5;
    int tier = lane & 1;                 // K-half: [tier*64, tier*64+64)
    int unit = warp * 16 + (lane >> 1);  // hidden unit 0..127
    const float* whh = dir ? whh_b : whh_f;
    const float* bhh = dir ? bhh_b : bhh_f;

    __shared__ __align__(16) float hbuf[2][128];

    u64 wR[32], wZ[32], wN[32];
    {
        const u64* pR = reinterpret_cast<const u64*>(whh + (size_t)unit * 128 + tier * 64);
        const u64* pZ = reinterpret_cast<const u64*>(whh + (size_t)(128 + unit) * 128 + tier * 64);
        const u64* pN = reinterpret_cast<const u64*>(whh + (size_t)(256 + unit) * 128 + tier * 64);
#pragma unroll
        for (int k = 0; k < 32; k++) { wR[k] = pR[k]; wZ[k] = pZ[k]; wN[k] = pN[k]; }
    }
    float br = bhh[unit], bz = bhh[128 + unit], bn = bhh[256 + unit];
    if (tid < 128) hbuf[0][tid] = 0.f;
    float hprev = 0.f;

    const float* x3p = d_x3 + (size_t)b * T * 768 + dir * 384
                       + (dir ? (size_t)(T - 1) * 768 : 0);
    const long xstep = dir ? -768 : 768;
    float* hsp = d_hs + ((size_t)dir * BT + (size_t)b * T) * D
                 + (dir ? (size_t)(T - 1) * D : 0) + unit;
    const long hstep = dir ? -(long)D : (long)D;

    float xr = x3p[unit], xz = x3p[128 + unit], xn = x3p[256 + unit];
    __syncthreads();

    int p = 0;
    for (int s = 0; s < T; s++) {
        const ulonglong2* hv = reinterpret_cast<const ulonglong2*>(&hbuf[p][tier * 64]);
        u64 aR0 = 0, aR1 = 0, aZ0 = 0, aZ1 = 0, aN0 = 0, aN1 = 0;
#pragma unroll
        for (int k = 0; k < 16; k++) {
            ulonglong2 h2 = hv[k];
            aR0 = ffma2(wR[2 * k],     h2.x, aR0);
            aR1 = ffma2(wR[2 * k + 1], h2.y, aR1);
            aZ0 = ffma2(wZ[2 * k],     h2.x, aZ0);
            aZ1 = ffma2(wZ[2 * k + 1], h2.y, aZ1);
            aN0 = ffma2(wN[2 * k],     h2.x, aN0);
            aN1 = ffma2(wN[2 * k + 1], h2.y, aN1);
        }
        float2 fr0 = u2f2(aR0), fr1 = u2f2(aR1);
        float2 fz0 = u2f2(aZ0), fz1 = u2f2(aZ1);
        float2 fn0 = u2f2(aN0), fn1 = u2f2(aN1);
        float rp = (fr0.x + fr0.y) + (fr1.x + fr1.y);
        float zp = (fz0.x + fz0.y) + (fz1.x + fz1.y);
        float np = (fn0.x + fn0.y) + (fn1.x + fn1.y);
        rp += __shfl_xor_sync(0xffffffffu, rp, 1);
        zp += __shfl_xor_sync(0xffffffffu, zp, 1);
        np += __shfl_xor_sync(0xffffffffu, np, 1);

        // prefetch next-step x (drains under the activation + barrier)
        float nxr = 0.f, nxz = 0.f, nxn = 0.f;
        if (s + 1 < T) {
            const float* xp = x3p + xstep;
            nxr = xp[unit]; nxz = xp[128 + unit]; nxn = xp[256 + unit];
        }

        float r = sigmoid_ap(xr + rp + br);
        float z = sigmoid_ap(xz + zp + bz);
        float n = tanh_ap(xn + r * (np + bn));
        float hnew = (1.f - z) * n + z * hprev;
        hprev = hnew;
        if (tier == 0) {
            hbuf[p ^ 1][unit] = hnew;
            *hsp = hnew;
        }
        hsp += hstep; x3p += xstep;
        xr = nxr; xz = nxz; xn = nxn;
        __syncthreads();
        p ^= 1;
    }
}

// ---------------- 4a) attention scores + softmax + last ----------------
__global__ void __launch_bounds__(512, 1)
attn1_kernel(const float* __restrict__ aw, const float* __restrict__ ab) {
    int b = blockIdx.x;
    int tid = threadIdx.x;  // 512
    __shared__ float aw_sh[256];
    __shared__ float sc[128];
    __shared__ int   msk[128];

    if (tid < 256) aw_sh[tid] = aw[tid];
    if (tid < T) msk[tid] = d_mask[b * T + tid];
    __syncthreads();

    const float* hf = d_hs + (size_t)b * T * D;
    const float* hb = d_hs + ((size_t)BT + (size_t)b * T) * D;
    int w = tid >> 5, lane = tid & 31;

    for (int t = w; t < T; t += 16) {
        float s = 0.f;
        const float* pf = hf + (size_t)t * D;
        const float* pb = hb + (size_t)t * D;
#pragma unroll
        for (int d = lane; d < D; d += 32)
            s += pf[d] * aw_sh[d] + pb[d] * aw_sh[128 + d];
#pragma unroll
        for (int o = 16; o; o >>= 1) s += __shfl_xor_sync(0xffffffffu, s, o);
        if (lane == 0) sc[t] = msk[t] ? (s + ab[0]) : -1e9f;
    }
    __syncthreads();

    if (w == 0) {
        float m = -1e30f;
        for (int t = lane; t < T; t += 32) m = fmaxf(m, sc[t]);
#pragma unroll
        for (int o = 16; o; o >>= 1) m = fmaxf(m, __shfl_xor_sync(0xffffffffu, m, o));
        float s = 0.f;
        for (int t = lane; t < T; t += 32) { float e = __expf(sc[t] - m); sc[t] = e; s += e; }
#pragma unroll
        for (int o = 16; o; o >>= 1) s += __shfl_xor_sync(0xffffffffu, s, o);
        float inv = 1.f / s;
        for (int t = lane; t < T; t += 32) d_attnw[b * 128 + t] = sc[t] * inv;
        int c = 0;
        for (int t = lane; t < T; t += 32) c += msk[t];
#pragma unroll
        for (int o = 16; o; o >>= 1) c += __shfl_xor_sync(0xffffffffu, c, o);
        if (lane == 0) d_last[b] = c - 1;
    }
}

// ---------------- 4b) context + h_last, grid (32, 2), 128 threads ----------------
__global__ void attn2_kernel() {
    int b = blockIdx.x, dir = blockIdx.y;
    int f = threadIdx.x;  // 128
    __shared__ float a_sh[128];
    if (f < T) a_sh[f] = d_attnw[b * 128 + f];
    __syncthreads();
    int last = d_last[b];

    const float* hcol = d_hs + ((size_t)dir * BT + (size_t)b * T) * D + f;
    float cacc = 0.f;
#pragma unroll
    for (int t0 = 0; t0 < T; t0 += 10) {
        float p = 0.f;
#pragma unroll
        for (int u = 0; u < 10; u++)
            p += a_sh[t0 + u] * hcol[(size_t)(t0 + u) * D];
        cacc += p;
    }
    d_ctx[b * 512 + dir * 128 + f] = cacc;
    d_ctx[b * 512 + 256 + dir * 128 + f] = hcol[(size_t)last * D];
}

// ---------------- 4c) combine ----------------
__global__ void comb_kernel(const float* __restrict__ comb_w, const float* __restrict__ comb_b) {
    int b = blockIdx.x, og = blockIdx.y;
    int tid = threadIdx.x, w = tid >> 5, lane = tid & 31;
    __shared__ __align__(16) float ctx[512];
    ctx[tid] = d_ctx[b * 512 + tid];
    ctx[256 + tid] = d_ctx[b * 512 + 256 + tid];
    __syncthreads();

    int o = og * 16 + 2 * w;
    const float4* rowA = reinterpret_cast<const float4*>(comb_w + (size_t)o * 512);
    const float4* rowB = reinterpret_cast<const float4*>(comb_w + (size_t)(o + 1) * 512);
    float accA = 0.f, accB = 0.f;
#pragma unroll
    for (int q = 0; q < 4; q++) {
        int i = lane + 32 * q;
        float4 wa = __ldcs(&rowA[i]);
        float4 wb = __ldcs(&rowB[i]);
        float4 iv = *reinterpret_cast<const float4*>(&ctx[4 * i]);
        accA += wa.x * iv.x + wa.y * iv.y + wa.z * iv.z + wa.w * iv.w;
        accB += wb.x * iv.x + wb.y * iv.y + wb.z * iv.z + wb.w * iv.w;
    }
#pragma unroll
    for (int of = 16; of; of >>= 1) {
        accA += __shfl_xor_sync(0xffffffffu, accA, of);
        accB += __shfl_xor_sync(0xffffffffu, accB, of);
    }
    if (lane == 0) {
        d_feat[b * D + o]     = tanh_ap(accA + comb_b[o]);
        d_feat[b * D + o + 1] = tanh_ap(accB + comb_b[o + 1]);
    }
}

// ---------------- 5) logits = feat @ fc_w^T + fc_b ----------------
#define FS 132
__global__ void logits_kernel(const float* __restrict__ fc_w, const float* __restrict__ fc_b,
                              float* __restrict__ out) {
    int o0 = blockIdx.x * 8;
    int tid = threadIdx.x;
    __shared__ __align__(16) float fsh[32 * FS];
    __shared__ __align__(16) float wsh[8 * 128];
    for (int i = tid; i < 32 * 32; i += 256) {
        int bb = i >> 5, k4 = i & 31;
        *reinterpret_cast<float4*>(&fsh[bb * FS + 4 * k4]) =
            *reinterpret_cast<const float4*>(&d_feat[bb * D + 4 * k4]);
    }
    for (int i = tid; i < 8 * 32; i += 256)
        *reinterpret_cast<float4*>(&wsh[4 * i]) =
            __ldcs(reinterpret_cast<const float4*>(&fc_w[(size_t)o0 * 128 + 4 * i]));
    __syncthreads();

    int bb = tid & 31, oj = tid >> 5;
    float acc = fc_b[o0 + oj];
#pragma unroll
    for (int k = 0; k < 128; k += 4) {
        float4 fv = *reinterpret_cast<const float4*>(&fsh[bb * FS + k]);
        float4 wv = *reinterpret_cast<const float4*>(&wsh[oj * 128 + k]);
        acc += fv.x * wv.x + fv.y * wv.y + fv.z * wv.z + fv.w * wv.w;
    }
    out[(size_t)bb * OUTN + o0 + oj] = acc;
}

// ---------------- launch ----------------
extern "C" void kernel_launch(void* const* d_in, const int* in_sizes, int n_in,
                              void* d_out, int out_size) {
    const float* x      = (const float*)d_in[0];
    const float* emb    = (const float*)d_in[1];
    const float* wih_f  = (const float*)d_in[2];
    const float* whh_f  = (const float*)d_in[3];
    const float* bih_f  = (const float*)d_in[4];
    const float* bhh_f  = (const float*)d_in[5];
    const float* wih_b  = (const float*)d_in[6];
    const float* whh_b  = (const float*)d_in[7];
    const float* bih_b  = (const float*)d_in[8];
    const float* bhh_b  = (const float*)d_in[9];
    const float* attn_w = (const float*)d_in[10];
    const float* attn_b = (const float*)d_in[11];
    const float* comb_w = (const float*)d_in[12];
    const float* comb_b = (const float*)d_in[13];
    const float* fc_w   = (const float*)d_in[14];
    const float* fc_b   = (const float*)d_in[15];
    float* out = (float*)d_out;

    embed_kernel<<<BT, 512>>>(x, emb);
    xgemm_kernel<<<dim3(100, 8, 2), 256>>>(wih_f, wih_b, bih_f, bih_b);
    gru_kernel<<<dim3(32, 2), 256>>>(whh_f, whh_b, bhh_f, bhh_b);
    attn1_kernel<<<32, 512>>>(attn_w, attn_b);
    attn2_kernel<<<dim3(32, 2), 128>>>();
    comb_kernel<<<dim3(32, 8), 256>>>(comb_w, comb_b);
    logits_kernel<<<125, 256>>>(fc_w, fc_b, out);
}